// round 7
// baseline (speedup 1.0000x reference)
#include <cuda_runtime.h>
#include <cuda_bf16.h>
#include <cuda_fp16.h>
#include <cstdint>
#include <math.h>

#define NTOK  16384
#define DM    1536
#define QKVD  2304

// ---- scratch (__device__ globals; no allocations allowed) ----
__device__ __nv_bfloat16 g_xh[(size_t)NTOK * DM],   g_xl[(size_t)NTOK * DM];
__device__ __nv_bfloat16 g_wqh[(size_t)QKVD * DM],  g_wql[(size_t)QKVD * DM];
__device__ __nv_bfloat16 g_woh[(size_t)DM * DM],    g_wol[(size_t)DM * DM];
__device__ __nv_bfloat16 g_qkvh[(size_t)NTOK * QKVD], g_qkvl[(size_t)NTOK * QKVD];
__device__ __nv_bfloat16 g_ath[(size_t)NTOK * DM],  g_atl[(size_t)NTOK * DM];
__device__ float g_cos[1024], g_sin[1024];

// ---- helpers ----
__device__ __forceinline__ uint32_t pack_bf2(__nv_bfloat16 a, __nv_bfloat16 b) {
    __nv_bfloat162 t = __halves2bfloat162(a, b);
    return *reinterpret_cast<uint32_t*>(&t);
}

__device__ __forceinline__ void split2(float x, float y, uint32_t& hi, uint32_t& lo) {
    __nv_bfloat16 hx = __float2bfloat16(x);
    __nv_bfloat16 hy = __float2bfloat16(y);
    __nv_bfloat16 lx = __float2bfloat16(x - __bfloat162float(hx));
    __nv_bfloat16 ly = __float2bfloat16(y - __bfloat162float(hy));
    hi = pack_bf2(hx, hy);
    lo = pack_bf2(lx, ly);
}

__device__ __forceinline__ void mma_bf16(float* c, uint32_t a0, uint32_t a1, uint32_t a2, uint32_t a3,
                                         uint32_t b0, uint32_t b1) {
    asm volatile(
        "mma.sync.aligned.m16n8k16.row.col.f32.bf16.bf16.f32 "
        "{%0,%1,%2,%3},{%4,%5,%6,%7},{%8,%9},{%0,%1,%2,%3};\n"
        : "+f"(c[0]), "+f"(c[1]), "+f"(c[2]), "+f"(c[3])
        : "r"(a0), "r"(a1), "r"(a2), "r"(a3), "r"(b0), "r"(b1));
}

__device__ __forceinline__ uint32_t smem_u32(const void* p) {
    return (uint32_t)__cvta_generic_to_shared(p);
}

__device__ __forceinline__ void cp16(uint32_t dst, const void* src) {
    asm volatile("cp.async.cg.shared.global [%0], [%1], 16;" :: "r"(dst), "l"(src));
}

// ---------------------------------------------------------------------------
// Split fp32 -> bf16 hi/lo planes
// ---------------------------------------------------------------------------
__global__ __launch_bounds__(256) void split_kernel(const float4* __restrict__ src,
                                                    uint32_t* __restrict__ h,
                                                    uint32_t* __restrict__ l, int n4) {
    int i = blockIdx.x * 256 + threadIdx.x;
    if (i < n4) {
        float4 v = src[i];
        uint32_t h0, l0, h1, l1;
        split2(v.x, v.y, h0, l0);
        split2(v.z, v.w, h1, l1);
        h[2 * i] = h0; h[2 * i + 1] = h1;
        l[2 * i] = l0; l[2 * i + 1] = l1;
    }
}

// ---------------------------------------------------------------------------
// RoPE tables
// ---------------------------------------------------------------------------
__global__ void rope_table_kernel() {
    int i = threadIdx.x;
    if (i < 1024) {
        int r = i >> 4, j = i & 15;
        int pos = (r < 32) ? r : (r < 48 ? r - 32 : r - 48);
        float inv = powf(10000.0f, -(float)j / 16.0f);
        float ang = (float)pos * inv;
        float s, c;
        sincosf(ang, &s, &c);
        g_cos[i] = c;
        g_sin[i] = s;
    }
}

// ---------------------------------------------------------------------------
// RoPE on q (scaled by log2e/sqrt(96)) and k, on bf16 hi/lo planes
// ---------------------------------------------------------------------------
__global__ __launch_bounds__(256) void rope_kernel() {
    const float SC2 = 1.4426950408889634f * 0.10206207261596575f;
    int tok = blockIdx.x;
    int t  = (tok >> 8) & 31;
    int s  = tok & 255;
    int rh = s >> 4, cw = s & 15;
    __nv_bfloat16* ph = g_qkvh + (size_t)tok * QKVD;
    __nv_bfloat16* pl = g_qkvl + (size_t)tok * QKVD;
    for (int i = threadIdx.x; i < 960; i += 256) {
        int head = i / 48, p = i % 48;
        int chunk = p >> 4, j = p & 15;
        int col0 = (head < 16 ? head * 96 : 1536 + (head - 16) * 96) + chunk * 32 + j;
        int pos = (chunk == 0) ? t : (chunk == 1 ? 32 + rh : 48 + cw);
        float c = g_cos[pos * 16 + j], sn = g_sin[pos * 16 + j];
        float x1 = __bfloat162float(ph[col0])      + __bfloat162float(pl[col0]);
        float x2 = __bfloat162float(ph[col0 + 16]) + __bfloat162float(pl[col0 + 16]);
        float y1 = x1 * c - x2 * sn;
        float y2 = x2 * c + x1 * sn;
        if (head < 16) { y1 *= SC2; y2 *= SC2; }
        __nv_bfloat16 h1 = __float2bfloat16(y1);
        __nv_bfloat16 h2 = __float2bfloat16(y2);
        ph[col0]      = h1;  pl[col0]      = __float2bfloat16(y1 - __bfloat162float(h1));
        ph[col0 + 16] = h2;  pl[col0 + 16] = __float2bfloat16(y2 - __bfloat162float(h2));
    }
}

// ---------------------------------------------------------------------------
// BF16x3 GEMM v2: C[M,N] = A[M,K]*B[N,K]^T.
// CTA 128x256, 8 warps (2x4), warp tile 64x64, BK=16, cp.async double buffer.
// smem stride 12 u32/row (conflict-free: (12r+tg)%32 covers all banks).
// ---------------------------------------------------------------------------
template<int SPLIT_OUT>
__global__ __launch_bounds__(256) void gemm_v2(
    const __nv_bfloat16* __restrict__ Ah, const __nv_bfloat16* __restrict__ Al,
    const __nv_bfloat16* __restrict__ Bh, const __nv_bfloat16* __restrict__ Bl,
    float* __restrict__ C, __nv_bfloat16* __restrict__ Ch, __nv_bfloat16* __restrict__ Cl,
    int M, int N, int K)
{
    extern __shared__ uint32_t dsm32[];   // 2 stages x 9216 u32 (Ah 1536 | Al 1536 | Bh 3072 | Bl 3072)
    const uint32_t sbase = smem_u32(dsm32);

    const int tid = threadIdx.x, warp = tid >> 5, lane = tid & 31;
    const int g = lane >> 2, tg = lane & 3;
    const int m0 = blockIdx.y * 128, n0 = blockIdx.x * 256;
    const int wm = (warp >> 2) * 64, wn = (warp & 3) * 64;

    float acc[4][8][4];
    #pragma unroll
    for (int i = 0; i < 4; i++)
        #pragma unroll
        for (int j = 0; j < 8; j++)
            #pragma unroll
            for (int e = 0; e < 4; e++) acc[i][j][e] = 0.f;

    const int rowA = tid >> 1, chA = tid & 1;

    auto load_stage = [&](int stg, int kofs) {
        uint32_t b = sbase + stg * 36864;
        cp16(b +         rowA * 48 + chA * 16, Ah + (size_t)(m0 + rowA) * K + kofs + chA * 8);
        cp16(b + 6144  + rowA * 48 + chA * 16, Al + (size_t)(m0 + rowA) * K + kofs + chA * 8);
        #pragma unroll
        for (int p = 0; p < 2; p++) {
            int idx = tid + p * 256;
            int rowB = idx >> 1, chB = idx & 1;
            cp16(b + 12288 + rowB * 48 + chB * 16, Bh + (size_t)(n0 + rowB) * K + kofs + chB * 8);
            cp16(b + 24576 + rowB * 48 + chB * 16, Bl + (size_t)(n0 + rowB) * K + kofs + chB * 8);
        }
    };

    const int KT = K / 16;
    load_stage(0, 0);
    asm volatile("cp.async.commit_group;");

    for (int kt = 0; kt < KT; kt++) {
        if (kt + 1 < KT) load_stage((kt + 1) & 1, (kt + 1) * 16);
        asm volatile("cp.async.commit_group;");
        asm volatile("cp.async.wait_group 1;" ::: "memory");
        __syncthreads();

        const uint32_t* S   = dsm32 + (kt & 1) * 9216;
        const uint32_t* sAh = S;
        const uint32_t* sAl = S + 1536;
        const uint32_t* sBh = S + 3072;
        const uint32_t* sBl = S + 6144;

        uint32_t fah[4][4], fal[4][4];
        #pragma unroll
        for (int i = 0; i < 4; i++) {
            int r = (wm + 16 * i + g) * 12 + tg;
            int r8 = r + 96;
            fah[i][0] = sAh[r]; fah[i][1] = sAh[r8]; fah[i][2] = sAh[r + 4]; fah[i][3] = sAh[r8 + 4];
            fal[i][0] = sAl[r]; fal[i][1] = sAl[r8]; fal[i][2] = sAl[r + 4]; fal[i][3] = sAl[r8 + 4];
        }
        #pragma unroll
        for (int j = 0; j < 8; j++) {
            int nb = (wn + 8 * j + g) * 12 + tg;
            uint32_t bh0 = sBh[nb], bh1 = sBh[nb + 4];
            uint32_t bl0 = sBl[nb], bl1 = sBl[nb + 4];
            #pragma unroll
            for (int i = 0; i < 4; i++) {
                mma_bf16(acc[i][j], fah[i][0], fah[i][1], fah[i][2], fah[i][3], bh0, bh1);
                mma_bf16(acc[i][j], fah[i][0], fah[i][1], fah[i][2], fah[i][3], bl0, bl1);
                mma_bf16(acc[i][j], fal[i][0], fal[i][1], fal[i][2], fal[i][3], bh0, bh1);
            }
        }
        __syncthreads();
    }

    #pragma unroll
    for (int i = 0; i < 4; i++)
        #pragma unroll
        for (int j = 0; j < 8; j++) {
            int row = m0 + wm + 16 * i + g;
            int col = n0 + wn + 8 * j + 2 * tg;
            if (SPLIT_OUT) {
                uint32_t h0, l0, h1, l1;
                split2(acc[i][j][0], acc[i][j][1], h0, l0);
                split2(acc[i][j][2], acc[i][j][3], h1, l1);
                *(uint32_t*)(Ch + (size_t)row * N + col)       = h0;
                *(uint32_t*)(Cl + (size_t)row * N + col)       = l0;
                *(uint32_t*)(Ch + (size_t)(row + 8) * N + col) = h1;
                *(uint32_t*)(Cl + (size_t)(row + 8) * N + col) = l1;
            } else {
                *(float2*)(C + (size_t)row * N + col)       = make_float2(acc[i][j][0], acc[i][j][1]);
                *(float2*)(C + (size_t)(row + 8) * N + col) = make_float2(acc[i][j][2], acc[i][j][3]);
            }
        }
}

// ---------------------------------------------------------------------------
// Attention: CTA = (b,t,head,64-query tile), 128 threads (4 warps x 16 rows).
// Flash-style, no-max softmax with f16x2 ex2, bf16x3 mma.sync.
// ---------------------------------------------------------------------------
__global__ __launch_bounds__(128) void attn_kernel() {
    extern __shared__ __nv_bfloat16 smb[];
    __nv_bfloat16* Qh = smb;                 // [64][120]
    __nv_bfloat16* Ql = Qh + 7680;
    __nv_bfloat16* Kh = Ql + 7680;           // [64][120]
    __nv_bfloat16* Kl = Kh + 7680;
    __nv_bfloat16* Vh = Kl + 7680;           // transposed [96][72]
    __nv_bfloat16* Vl = Vh + 6912;

    const int tid = threadIdx.x, warp = tid >> 5, lane = tid & 31;
    const int g = lane >> 2, tg = lane & 3;
    const int bid = blockIdx.x;
    const int qt = bid & 3, h = (bid >> 2) & 15, bt = bid >> 6, grp = h >> 2;
    const size_t tokbase = (size_t)bt * 256;

    #pragma unroll
    for (int t = 0; t < 6; t++) {
        int u = tid + t * 128;
        int row = u / 12, c8 = u % 12;
        size_t gb = (tokbase + qt * 64 + row) * QKVD + h * 96 + c8 * 8;
        *(uint4*)(Qh + row * 120 + c8 * 8) = *(const uint4*)(g_qkvh + gb);
        *(uint4*)(Ql + row * 120 + c8 * 8) = *(const uint4*)(g_qkvl + gb);
    }

    const uint32_t* Q32h = (const uint32_t*)Qh;
    const uint32_t* Q32l = (const uint32_t*)Ql;
    const uint32_t* K32h = (const uint32_t*)Kh;
    const uint32_t* K32l = (const uint32_t*)Kl;
    const uint32_t* V32h = (const uint32_t*)Vh;
    const uint32_t* V32l = (const uint32_t*)Vl;

    float acc[12][4];
    #pragma unroll
    for (int j = 0; j < 12; j++)
        #pragma unroll
        for (int e = 0; e < 4; e++) acc[j][e] = 0.f;
    float rs0 = 0.f, rs1 = 0.f;

    for (int c = 0; c < 4; c++) {
        #pragma unroll
        for (int t = 0; t < 6; t++) {
            int u = tid + t * 128;
            int row = u / 12, c8 = u % 12;
            size_t gb = (tokbase + c * 64 + row) * QKVD + 1536 + grp * 96 + c8 * 8;
            *(uint4*)(Kh + row * 120 + c8 * 8) = *(const uint4*)(g_qkvh + gb);
            *(uint4*)(Kl + row * 120 + c8 * 8) = *(const uint4*)(g_qkvl + gb);
        }
        #pragma unroll
        for (int t = 0; t < 24; t++) {
            int u = tid + t * 128;
            int key = u / 48, d = (u % 48) * 2;
            size_t gb = (tokbase + c * 64 + key) * QKVD + 1920 + grp * 96 + d;
            __nv_bfloat162 ph = *(const __nv_bfloat162*)(g_qkvh + gb);
            __nv_bfloat162 pl = *(const __nv_bfloat162*)(g_qkvl + gb);
            Vh[d * 72 + key] = ph.x; Vh[(d + 1) * 72 + key] = ph.y;
            Vl[d * 72 + key] = pl.x; Vl[(d + 1) * 72 + key] = pl.y;
        }
        __syncthreads();

        float s[8][4];
        #pragma unroll
        for (int j = 0; j < 8; j++)
            #pragma unroll
            for (int e = 0; e < 4; e++) s[j][e] = 0.f;

        #pragma unroll
        for (int ks = 0; ks < 6; ks++) {
            int r = (warp * 16 + g) * 60 + ks * 8 + tg;
            int r8 = r + 480;
            uint32_t a0h = Q32h[r], a1h = Q32h[r8], a2h = Q32h[r + 4], a3h = Q32h[r8 + 4];
            uint32_t a0l = Q32l[r], a1l = Q32l[r8], a2l = Q32l[r + 4], a3l = Q32l[r8 + 4];
            #pragma unroll
            for (int j = 0; j < 8; j++) {
                int nb = (j * 8 + g) * 60 + ks * 8 + tg;
                uint32_t bh0 = K32h[nb], bh1 = K32h[nb + 4];
                uint32_t bl0 = K32l[nb], bl1 = K32l[nb + 4];
                mma_bf16(s[j], a0h, a1h, a2h, a3h, bh0, bh1);
                mma_bf16(s[j], a0h, a1h, a2h, a3h, bl0, bl1);
                mma_bf16(s[j], a0l, a1l, a2l, a3l, bh0, bh1);
            }
        }

        // probs = 2^score via f16x2 MUFU (2 exps per op)
        #pragma unroll
        for (int j = 0; j < 8; j++) {
            __half2 ha = __floats2half2_rn(s[j][0], s[j][1]);
            __half2 hb = __floats2half2_rn(s[j][2], s[j][3]);
            uint32_t ua = *reinterpret_cast<uint32_t*>(&ha);
            uint32_t ub = *reinterpret_cast<uint32_t*>(&hb);
            asm("ex2.approx.f16x2 %0, %0;" : "+r"(ua));
            asm("ex2.approx.f16x2 %0, %0;" : "+r"(ub));
            ha = *reinterpret_cast<__half2*>(&ua);
            hb = *reinterpret_cast<__half2*>(&ub);
            float2 fa = __half22float2(ha), fb = __half22float2(hb);
            s[j][0] = fa.x; s[j][1] = fa.y; s[j][2] = fb.x; s[j][3] = fb.y;
            rs0 += fa.x + fa.y;
            rs1 += fb.x + fb.y;
        }

        #pragma unroll
        for (int kk = 0; kk < 4; kk++) {
            uint32_t A0h, A0l, A1h, A1l, A2h, A2l, A3h, A3l;
            split2(s[2 * kk][0],     s[2 * kk][1],     A0h, A0l);
            split2(s[2 * kk][2],     s[2 * kk][3],     A1h, A1l);
            split2(s[2 * kk + 1][0], s[2 * kk + 1][1], A2h, A2l);
            split2(s[2 * kk + 1][2], s[2 * kk + 1][3], A3h, A3l);
            #pragma unroll
            for (int j = 0; j < 12; j++) {
                int vb = (j * 8 + g) * 36 + kk * 8 + tg;
                uint32_t bh0 = V32h[vb], bh1 = V32h[vb + 4];
                uint32_t bl0 = V32l[vb], bl1 = V32l[vb + 4];
                mma_bf16(acc[j], A0h, A1h, A2h, A3h, bh0, bh1);
                mma_bf16(acc[j], A0h, A1h, A2h, A3h, bl0, bl1);
                mma_bf16(acc[j], A0l, A1l, A2l, A3l, bh0, bh1);
            }
        }
        __syncthreads();
    }

    rs0 += __shfl_xor_sync(0xffffffffu, rs0, 1);
    rs0 += __shfl_xor_sync(0xffffffffu, rs0, 2);
    rs1 += __shfl_xor_sync(0xffffffffu, rs1, 1);
    rs1 += __shfl_xor_sync(0xffffffffu, rs1, 2);
    float i0 = 1.f / rs0, i1 = 1.f / rs1;

    int tok0 = bt * 256 + qt * 64 + warp * 16 + g;
    #pragma unroll
    for (int j = 0; j < 12; j++) {
        int col = h * 96 + j * 8 + 2 * tg;
        uint32_t h0, l0, h1, l1;
        split2(acc[j][0] * i0, acc[j][1] * i0, h0, l0);
        split2(acc[j][2] * i1, acc[j][3] * i1, h1, l1);
        *(uint32_t*)(g_ath + (size_t)tok0 * DM + col)       = h0;
        *(uint32_t*)(g_atl + (size_t)tok0 * DM + col)       = l0;
        *(uint32_t*)(g_ath + (size_t)(tok0 + 8) * DM + col) = h1;
        *(uint32_t*)(g_atl + (size_t)(tok0 + 8) * DM + col) = l1;
    }
}

// ---------------------------------------------------------------------------
extern "C" void kernel_launch(void* const* d_in, const int* in_sizes, int n_in,
                              void* d_out, int out_size) {
    (void)in_sizes; (void)n_in; (void)out_size;
    const float* x     = (const float*)d_in[0];
    const float* w_qkv = (const float*)d_in[2];
    const float* w_o   = (const float*)d_in[3];
    float* out = (float*)d_out;

    __nv_bfloat16 *xh, *xl, *wqh, *wql, *woh, *wol, *qkvh, *qkvl, *ath, *atl;
    cudaGetSymbolAddress((void**)&xh, g_xh);     cudaGetSymbolAddress((void**)&xl, g_xl);
    cudaGetSymbolAddress((void**)&wqh, g_wqh);   cudaGetSymbolAddress((void**)&wql, g_wql);
    cudaGetSymbolAddress((void**)&woh, g_woh);   cudaGetSymbolAddress((void**)&wol, g_wol);
    cudaGetSymbolAddress((void**)&qkvh, g_qkvh); cudaGetSymbolAddress((void**)&qkvl, g_qkvl);
    cudaGetSymbolAddress((void**)&ath, g_ath);   cudaGetSymbolAddress((void**)&atl, g_atl);

    cudaFuncSetAttribute(attn_kernel, cudaFuncAttributeMaxDynamicSharedMemorySize, 89088);
    cudaFuncSetAttribute(gemm_v2<0>, cudaFuncAttributeMaxDynamicSharedMemorySize, 73728);
    cudaFuncSetAttribute(gemm_v2<1>, cudaFuncAttributeMaxDynamicSharedMemorySize, 73728);

    rope_table_kernel<<<1, 1024>>>();
    split_kernel<<<24576, 256>>>((const float4*)x,     (uint32_t*)xh,  (uint32_t*)xl,  6291456);
    split_kernel<<<3456,  256>>>((const float4*)w_qkv, (uint32_t*)wqh, (uint32_t*)wql, 884736);
    split_kernel<<<2304,  256>>>((const float4*)w_o,   (uint32_t*)woh, (uint32_t*)wol, 589824);

    dim3 g1(QKVD / 256, NTOK / 128);   // 9 x 128
    gemm_v2<1><<<g1, 256, 73728>>>(xh, xl, wqh, wql, nullptr, qkvh, qkvl, NTOK, QKVD, DM);

    rope_kernel<<<NTOK, 256>>>();

    attn_kernel<<<4096, 128, 89088>>>();

    dim3 g2(DM / 256, NTOK / 128);     // 6 x 128
    gemm_v2<0><<<g2, 256, 73728>>>(ath, atl, woh, wol, out, nullptr, nullptr, NTOK, DM, DM);
}

// round 8
// speedup vs baseline: 1.6739x; 1.6739x over previous
#include <cuda_runtime.h>
#include <cuda_bf16.h>
#include <cuda_fp16.h>
#include <cstdint>
#include <math.h>

#define NTOK  16384
#define DM    1536
#define QKVD  2304

// ---- scratch (__device__ globals; no allocations allowed) ----
__device__ __half g_xh[(size_t)NTOK * DM];
__device__ __half g_wqh[(size_t)QKVD * DM], g_wql[(size_t)QKVD * DM];
__device__ __half g_woh[(size_t)DM * DM],   g_wol[(size_t)DM * DM];
__device__ __half g_qkvh[(size_t)NTOK * QKVD], g_qkvl[(size_t)NTOK * QKVD];
__device__ __half g_ath[(size_t)NTOK * DM];
__device__ float g_cos[1024], g_sin[1024];

// ---- helpers ----
__device__ __forceinline__ void split2h(float x, float y, uint32_t& hi, uint32_t& lo) {
    __half hx = __float2half_rn(x), hy = __float2half_rn(y);
    __half lx = __float2half_rn(x - __half2float(hx));
    __half ly = __float2half_rn(y - __half2float(hy));
    __half2 H = __halves2half2(hx, hy), L = __halves2half2(lx, ly);
    hi = *reinterpret_cast<uint32_t*>(&H);
    lo = *reinterpret_cast<uint32_t*>(&L);
}

__device__ __forceinline__ uint32_t packh2(float x, float y) {
    __half2 t = __floats2half2_rn(x, y);
    return *reinterpret_cast<uint32_t*>(&t);
}

__device__ __forceinline__ void mma_f16(float* c, uint32_t a0, uint32_t a1, uint32_t a2, uint32_t a3,
                                        uint32_t b0, uint32_t b1) {
    asm volatile(
        "mma.sync.aligned.m16n8k16.row.col.f32.f16.f16.f32 "
        "{%0,%1,%2,%3},{%4,%5,%6,%7},{%8,%9},{%0,%1,%2,%3};\n"
        : "+f"(c[0]), "+f"(c[1]), "+f"(c[2]), "+f"(c[3])
        : "r"(a0), "r"(a1), "r"(a2), "r"(a3), "r"(b0), "r"(b1));
}

__device__ __forceinline__ float ex2f(float x) {
    float r;
    asm("ex2.approx.ftz.f32 %0, %1;" : "=f"(r) : "f"(x));
    return r;
}

// ---------------------------------------------------------------------------
// fp32 -> fp16 hi-only convert (for x)
// ---------------------------------------------------------------------------
__global__ __launch_bounds__(256) void cvt_kernel(const float4* __restrict__ src,
                                                  uint32_t* __restrict__ h, int n4) {
    int i = blockIdx.x * 256 + threadIdx.x;
    if (i < n4) {
        float4 v = src[i];
        h[2 * i]     = packh2(v.x, v.y);
        h[2 * i + 1] = packh2(v.z, v.w);
    }
}

// ---------------------------------------------------------------------------
// fp32 -> fp16 hi/lo split (for weights)
// ---------------------------------------------------------------------------
__global__ __launch_bounds__(256) void split_kernel(const float4* __restrict__ src,
                                                    uint32_t* __restrict__ h,
                                                    uint32_t* __restrict__ l, int n4) {
    int i = blockIdx.x * 256 + threadIdx.x;
    if (i < n4) {
        float4 v = src[i];
        uint32_t h0, l0, h1, l1;
        split2h(v.x, v.y, h0, l0);
        split2h(v.z, v.w, h1, l1);
        h[2 * i] = h0; h[2 * i + 1] = h1;
        l[2 * i] = l0; l[2 * i + 1] = l1;
    }
}

// ---------------------------------------------------------------------------
// RoPE tables
// ---------------------------------------------------------------------------
__global__ void rope_table_kernel() {
    int i = threadIdx.x;
    if (i < 1024) {
        int r = i >> 4, j = i & 15;
        int pos = (r < 32) ? r : (r < 48 ? r - 32 : r - 48);
        float inv = powf(10000.0f, -(float)j / 16.0f);
        float ang = (float)pos * inv;
        float s, c;
        sincosf(ang, &s, &c);
        g_cos[i] = c;
        g_sin[i] = s;
    }
}

// ---------------------------------------------------------------------------
// RoPE on q (scaled by log2e/sqrt(96)) and k, on fp16 hi/lo planes
// ---------------------------------------------------------------------------
__global__ __launch_bounds__(256) void rope_kernel() {
    const float SC2 = 1.4426950408889634f * 0.10206207261596575f;
    int tok = blockIdx.x;
    int t  = (tok >> 8) & 31;
    int s  = tok & 255;
    int rh = s >> 4, cw = s & 15;
    __half* ph = g_qkvh + (size_t)tok * QKVD;
    __half* pl = g_qkvl + (size_t)tok * QKVD;
    for (int i = threadIdx.x; i < 960; i += 256) {
        int head = i / 48, p = i % 48;
        int chunk = p >> 4, j = p & 15;
        int col0 = (head < 16 ? head * 96 : 1536 + (head - 16) * 96) + chunk * 32 + j;
        int pos = (chunk == 0) ? t : (chunk == 1 ? 32 + rh : 48 + cw);
        float c = g_cos[pos * 16 + j], sn = g_sin[pos * 16 + j];
        float x1 = __half2float(ph[col0])      + __half2float(pl[col0]);
        float x2 = __half2float(ph[col0 + 16]) + __half2float(pl[col0 + 16]);
        float y1 = x1 * c - x2 * sn;
        float y2 = x2 * c + x1 * sn;
        if (head < 16) { y1 *= SC2; y2 *= SC2; }
        __half h1 = __float2half_rn(y1);
        __half h2 = __float2half_rn(y2);
        ph[col0]      = h1;  pl[col0]      = __float2half_rn(y1 - __half2float(h1));
        ph[col0 + 16] = h2;  pl[col0 + 16] = __float2half_rn(y2 - __half2float(h2));
    }
}

// ---------------------------------------------------------------------------
// FP16x2 GEMM: C[M,N] = A[M,K]*B[N,K]^T;  A hi-plane only, B hi+lo planes.
// C ~= Ah*Bh + Ah*Bl  (A-quantization error ~1.4e-4, accepted).
// 128x128 tile, BK=32, 8 warps, warp tile 64x32, m16n8k16, reg-prefetch.
// ---------------------------------------------------------------------------
template<int SPLIT_OUT>
__global__ __launch_bounds__(256) void gemm_x2(
    const __half* __restrict__ Ah,
    const __half* __restrict__ Bh, const __half* __restrict__ Bl,
    float* __restrict__ C, __half* __restrict__ Ch, __half* __restrict__ Cl,
    int M, int N, int K)
{
    __shared__ __half sAh[128 * 40], sBh[128 * 40], sBl[128 * 40];

    const int tid = threadIdx.x, warp = tid >> 5, lane = tid & 31;
    const int g = lane >> 2, tg = lane & 3;
    const int m0 = blockIdx.y * 128, n0 = blockIdx.x * 128;
    const int wm = (warp >> 2) * 64, wn = (warp & 3) * 32;
    const int lrow = tid >> 1, lcol = (tid & 1) * 16;

    float acc[4][4][4];
    #pragma unroll
    for (int i = 0; i < 4; i++)
        #pragma unroll
        for (int j = 0; j < 4; j++)
            #pragma unroll
            for (int e = 0; e < 4; e++) acc[i][j][e] = 0.f;

    const __half* gAh = Ah + (size_t)(m0 + lrow) * K + lcol;
    const __half* gBh = Bh + (size_t)(n0 + lrow) * K + lcol;
    const __half* gBl = Bl + (size_t)(n0 + lrow) * K + lcol;

    uint4 pah[2], pbh[2], pbl[2];
    #define LD8(kt) do { \
        pah[0] = *(const uint4*)(gAh + (kt));     pah[1] = *(const uint4*)(gAh + (kt) + 8); \
        pbh[0] = *(const uint4*)(gBh + (kt));     pbh[1] = *(const uint4*)(gBh + (kt) + 8); \
        pbl[0] = *(const uint4*)(gBl + (kt));     pbl[1] = *(const uint4*)(gBl + (kt) + 8); \
    } while (0)

    LD8(0);

    const uint32_t* A32h = (const uint32_t*)sAh;
    const uint32_t* B32h = (const uint32_t*)sBh;
    const uint32_t* B32l = (const uint32_t*)sBl;

    for (int kt = 0; kt < K; kt += 32) {
        *(uint4*)(sAh + lrow * 40 + lcol) = pah[0]; *(uint4*)(sAh + lrow * 40 + lcol + 8) = pah[1];
        *(uint4*)(sBh + lrow * 40 + lcol) = pbh[0]; *(uint4*)(sBh + lrow * 40 + lcol + 8) = pbh[1];
        *(uint4*)(sBl + lrow * 40 + lcol) = pbl[0]; *(uint4*)(sBl + lrow * 40 + lcol + 8) = pbl[1];
        __syncthreads();
        if (kt + 32 < K) LD8(kt + 32);

        #pragma unroll
        for (int ks = 0; ks < 2; ks++) {
            uint32_t fah[4][4];
            #pragma unroll
            for (int i = 0; i < 4; i++) {
                int r = (wm + i * 16 + g) * 20 + ks * 8 + tg;
                int r8 = r + 160;
                fah[i][0] = A32h[r]; fah[i][1] = A32h[r8]; fah[i][2] = A32h[r + 4]; fah[i][3] = A32h[r8 + 4];
            }
            #pragma unroll
            for (int j = 0; j < 4; j++) {
                int nb = (wn + j * 8 + g) * 20 + ks * 8 + tg;
                uint32_t bh0 = B32h[nb], bh1 = B32h[nb + 4];
                uint32_t bl0 = B32l[nb], bl1 = B32l[nb + 4];
                #pragma unroll
                for (int i = 0; i < 4; i++) {
                    mma_f16(acc[i][j], fah[i][0], fah[i][1], fah[i][2], fah[i][3], bh0, bh1);
                    mma_f16(acc[i][j], fah[i][0], fah[i][1], fah[i][2], fah[i][3], bl0, bl1);
                }
            }
        }
        __syncthreads();
    }
    #undef LD8

    #pragma unroll
    for (int i = 0; i < 4; i++)
        #pragma unroll
        for (int j = 0; j < 4; j++) {
            int row = m0 + wm + i * 16 + g;
            int col = n0 + wn + j * 8 + 2 * tg;
            if (SPLIT_OUT) {
                uint32_t h0, l0, h1, l1;
                split2h(acc[i][j][0], acc[i][j][1], h0, l0);
                split2h(acc[i][j][2], acc[i][j][3], h1, l1);
                *(uint32_t*)(Ch + (size_t)row * N + col)       = h0;
                *(uint32_t*)(Cl + (size_t)row * N + col)       = l0;
                *(uint32_t*)(Ch + (size_t)(row + 8) * N + col) = h1;
                *(uint32_t*)(Cl + (size_t)(row + 8) * N + col) = l1;
            } else {
                *(float2*)(C + (size_t)row * N + col)       = make_float2(acc[i][j][0], acc[i][j][1]);
                *(float2*)(C + (size_t)(row + 8) * N + col) = make_float2(acc[i][j][2], acc[i][j][3]);
            }
        }
}

// ---------------------------------------------------------------------------
// Attention: CTA = (b,t,head,64-query tile), 128 threads (4 warps x 16 rows).
// Flash-style, no-max f32 ex2 softmax, fp16 x2 matmuls:
//   scores ~= Qh*Kh + Qh*Kl ;  out ~= Ph*Vh + Ph*Vl.
// ---------------------------------------------------------------------------
__global__ __launch_bounds__(128) void attn_kernel() {
    extern __shared__ __half smb[];
    __half* Qh = smb;                 // [64][120]
    __half* Kh = Qh + 7680;           // [64][120]
    __half* Kl = Kh + 7680;
    __half* Vh = Kl + 7680;           // transposed [96][72]
    __half* Vl = Vh + 6912;

    const int tid = threadIdx.x, warp = tid >> 5, lane = tid & 31;
    const int g = lane >> 2, tg = lane & 3;
    const int bid = blockIdx.x;
    const int qt = bid & 3, h = (bid >> 2) & 15, bt = bid >> 6, grp = h >> 2;
    const size_t tokbase = (size_t)bt * 256;

    #pragma unroll
    for (int t = 0; t < 6; t++) {
        int u = tid + t * 128;
        int row = u / 12, c8 = u % 12;
        size_t gb = (tokbase + qt * 64 + row) * QKVD + h * 96 + c8 * 8;
        *(uint4*)(Qh + row * 120 + c8 * 8) = *(const uint4*)(g_qkvh + gb);
    }

    const uint32_t* Q32h = (const uint32_t*)Qh;
    const uint32_t* K32h = (const uint32_t*)Kh;
    const uint32_t* K32l = (const uint32_t*)Kl;
    const uint32_t* V32h = (const uint32_t*)Vh;
    const uint32_t* V32l = (const uint32_t*)Vl;

    float acc[12][4];
    #pragma unroll
    for (int j = 0; j < 12; j++)
        #pragma unroll
        for (int e = 0; e < 4; e++) acc[j][e] = 0.f;
    float rs0 = 0.f, rs1 = 0.f;

    for (int c = 0; c < 4; c++) {
        #pragma unroll
        for (int t = 0; t < 6; t++) {
            int u = tid + t * 128;
            int row = u / 12, c8 = u % 12;
            size_t gb = (tokbase + c * 64 + row) * QKVD + 1536 + grp * 96 + c8 * 8;
            *(uint4*)(Kh + row * 120 + c8 * 8) = *(const uint4*)(g_qkvh + gb);
            *(uint4*)(Kl + row * 120 + c8 * 8) = *(const uint4*)(g_qkvl + gb);
        }
        #pragma unroll
        for (int t = 0; t < 24; t++) {
            int u = tid + t * 128;
            int key = u / 48, d = (u % 48) * 2;
            size_t gb = (tokbase + c * 64 + key) * QKVD + 1920 + grp * 96 + d;
            __half2 ph = *(const __half2*)(g_qkvh + gb);
            __half2 pl = *(const __half2*)(g_qkvl + gb);
            Vh[d * 72 + key] = __low2half(ph);  Vh[(d + 1) * 72 + key] = __high2half(ph);
            Vl[d * 72 + key] = __low2half(pl);  Vl[(d + 1) * 72 + key] = __high2half(pl);
        }
        __syncthreads();

        float s[8][4];
        #pragma unroll
        for (int j = 0; j < 8; j++)
            #pragma unroll
            for (int e = 0; e < 4; e++) s[j][e] = 0.f;

        #pragma unroll
        for (int ks = 0; ks < 6; ks++) {
            int r = (warp * 16 + g) * 60 + ks * 8 + tg;
            int r8 = r + 480;
            uint32_t a0 = Q32h[r], a1 = Q32h[r8], a2 = Q32h[r + 4], a3 = Q32h[r8 + 4];
            #pragma unroll
            for (int j = 0; j < 8; j++) {
                int nb = (j * 8 + g) * 60 + ks * 8 + tg;
                uint32_t bh0 = K32h[nb], bh1 = K32h[nb + 4];
                uint32_t bl0 = K32l[nb], bl1 = K32l[nb + 4];
                mma_f16(s[j], a0, a1, a2, a3, bh0, bh1);
                mma_f16(s[j], a0, a1, a2, a3, bl0, bl1);
            }
        }

        #pragma unroll
        for (int j = 0; j < 8; j++) {
            s[j][0] = ex2f(s[j][0]); s[j][1] = ex2f(s[j][1]);
            s[j][2] = ex2f(s[j][2]); s[j][3] = ex2f(s[j][3]);
            rs0 += s[j][0] + s[j][1];
            rs1 += s[j][2] + s[j][3];
        }

        #pragma unroll
        for (int kk = 0; kk < 4; kk++) {
            uint32_t A0 = packh2(s[2 * kk][0],     s[2 * kk][1]);
            uint32_t A1 = packh2(s[2 * kk][2],     s[2 * kk][3]);
            uint32_t A2 = packh2(s[2 * kk + 1][0], s[2 * kk + 1][1]);
            uint32_t A3 = packh2(s[2 * kk + 1][2], s[2 * kk + 1][3]);
            #pragma unroll
            for (int j = 0; j < 12; j++) {
                int vb = (j * 8 + g) * 36 + kk * 8 + tg;
                uint32_t bh0 = V32h[vb], bh1 = V32h[vb + 4];
                uint32_t bl0 = V32l[vb], bl1 = V32l[vb + 4];
                mma_f16(acc[j], A0, A1, A2, A3, bh0, bh1);
                mma_f16(acc[j], A0, A1, A2, A3, bl0, bl1);
            }
        }
        __syncthreads();
    }

    rs0 += __shfl_xor_sync(0xffffffffu, rs0, 1);
    rs0 += __shfl_xor_sync(0xffffffffu, rs0, 2);
    rs1 += __shfl_xor_sync(0xffffffffu, rs1, 1);
    rs1 += __shfl_xor_sync(0xffffffffu, rs1, 2);
    float i0 = 1.f / rs0, i1 = 1.f / rs1;

    int tok0 = bt * 256 + qt * 64 + warp * 16 + g;
    #pragma unroll
    for (int j = 0; j < 12; j++) {
        int col = h * 96 + j * 8 + 2 * tg;
        *(uint32_t*)(g_ath + (size_t)tok0 * DM + col)       = packh2(acc[j][0] * i0, acc[j][1] * i0);
        *(uint32_t*)(g_ath + (size_t)(tok0 + 8) * DM + col) = packh2(acc[j][2] * i1, acc[j][3] * i1);
    }
}

// ---------------------------------------------------------------------------
extern "C" void kernel_launch(void* const* d_in, const int* in_sizes, int n_in,
                              void* d_out, int out_size) {
    (void)in_sizes; (void)n_in; (void)out_size;
    const float* x     = (const float*)d_in[0];
    const float* w_qkv = (const float*)d_in[2];
    const float* w_o   = (const float*)d_in[3];
    float* out = (float*)d_out;

    __half *xh, *wqh, *wql, *woh, *wol, *qkvh, *qkvl, *ath;
    cudaGetSymbolAddress((void**)&xh, g_xh);
    cudaGetSymbolAddress((void**)&wqh, g_wqh);   cudaGetSymbolAddress((void**)&wql, g_wql);
    cudaGetSymbolAddress((void**)&woh, g_woh);   cudaGetSymbolAddress((void**)&wol, g_wol);
    cudaGetSymbolAddress((void**)&qkvh, g_qkvh); cudaGetSymbolAddress((void**)&qkvl, g_qkvl);
    cudaGetSymbolAddress((void**)&ath, g_ath);

    cudaFuncSetAttribute(attn_kernel, cudaFuncAttributeMaxDynamicSharedMemorySize, 73728);

    rope_table_kernel<<<1, 1024>>>();
    cvt_kernel<<<24576, 256>>>((const float4*)x, (uint32_t*)xh, 6291456);
    split_kernel<<<3456,  256>>>((const float4*)w_qkv, (uint32_t*)wqh, (uint32_t*)wql, 884736);
    split_kernel<<<2304,  256>>>((const float4*)w_o,   (uint32_t*)woh, (uint32_t*)wol, 589824);

    dim3 g1(QKVD / 128, NTOK / 128);
    gemm_x2<1><<<g1, 256>>>(xh, wqh, wql, nullptr, qkvh, qkvl, NTOK, QKVD, DM);

    rope_kernel<<<NTOK, 256>>>();

    attn_kernel<<<4096, 128, 73728>>>();

    dim3 g2(DM / 128, NTOK / 128);
    gemm_x2<0><<<g2, 256>>>(ath, woh, wol, out, nullptr, nullptr, NTOK, DM, DM);
}

// round 9
// speedup vs baseline: 1.9997x; 1.1946x over previous
#include <cuda_runtime.h>
#include <cuda_bf16.h>
#include <cuda_fp16.h>
#include <cstdint>
#include <math.h>

#define NTOK  16384
#define DM    1536
#define QKVD  2304

// ---- scratch (__device__ globals; no allocations allowed) ----
__device__ __half g_xh[(size_t)NTOK * DM];
__device__ __half g_wqh[(size_t)QKVD * DM], g_wql[(size_t)QKVD * DM];
__device__ __half g_woh[(size_t)DM * DM];
__device__ __half g_qkvh[(size_t)NTOK * QKVD], g_qkvl[(size_t)NTOK * QKVD];
__device__ __half g_ath[(size_t)NTOK * DM];
__device__ float g_cos[1024], g_sin[1024];

// ---- helpers ----
__device__ __forceinline__ void split2h(float x, float y, uint32_t& hi, uint32_t& lo) {
    __half hx = __float2half_rn(x), hy = __float2half_rn(y);
    __half lx = __float2half_rn(x - __half2float(hx));
    __half ly = __float2half_rn(y - __half2float(hy));
    __half2 H = __halves2half2(hx, hy), L = __halves2half2(lx, ly);
    hi = *reinterpret_cast<uint32_t*>(&H);
    lo = *reinterpret_cast<uint32_t*>(&L);
}

__device__ __forceinline__ uint32_t packh2(float x, float y) {
    __half2 t = __floats2half2_rn(x, y);
    return *reinterpret_cast<uint32_t*>(&t);
}

__device__ __forceinline__ void mma_f16(float* c, uint32_t a0, uint32_t a1, uint32_t a2, uint32_t a3,
                                        uint32_t b0, uint32_t b1) {
    asm volatile(
        "mma.sync.aligned.m16n8k16.row.col.f32.f16.f16.f32 "
        "{%0,%1,%2,%3},{%4,%5,%6,%7},{%8,%9},{%0,%1,%2,%3};\n"
        : "+f"(c[0]), "+f"(c[1]), "+f"(c[2]), "+f"(c[3])
        : "r"(a0), "r"(a1), "r"(a2), "r"(a3), "r"(b0), "r"(b1));
}

__device__ __forceinline__ float ex2f(float x) {
    float r;
    asm("ex2.approx.ftz.f32 %0, %1;" : "=f"(r) : "f"(x));
    return r;
}

// ---------------------------------------------------------------------------
// fp32 -> fp16 hi-only convert
// ---------------------------------------------------------------------------
__global__ __launch_bounds__(256) void cvt_kernel(const float4* __restrict__ src,
                                                  uint32_t* __restrict__ h, int n4) {
    int i = blockIdx.x * 256 + threadIdx.x;
    if (i < n4) {
        float4 v = src[i];
        h[2 * i]     = packh2(v.x, v.y);
        h[2 * i + 1] = packh2(v.z, v.w);
    }
}

// ---------------------------------------------------------------------------
// fp32 -> fp16 hi/lo split (for w_qkv)
// ---------------------------------------------------------------------------
__global__ __launch_bounds__(256) void split_kernel(const float4* __restrict__ src,
                                                    uint32_t* __restrict__ h,
                                                    uint32_t* __restrict__ l, int n4) {
    int i = blockIdx.x * 256 + threadIdx.x;
    if (i < n4) {
        float4 v = src[i];
        uint32_t h0, l0, h1, l1;
        split2h(v.x, v.y, h0, l0);
        split2h(v.z, v.w, h1, l1);
        h[2 * i] = h0; h[2 * i + 1] = h1;
        l[2 * i] = l0; l[2 * i + 1] = l1;
    }
}

// ---------------------------------------------------------------------------
// RoPE tables
// ---------------------------------------------------------------------------
__global__ void rope_table_kernel() {
    int i = threadIdx.x;
    if (i < 1024) {
        int r = i >> 4, j = i & 15;
        int pos = (r < 32) ? r : (r < 48 ? r - 32 : r - 48);
        float inv = powf(10000.0f, -(float)j / 16.0f);
        float ang = (float)pos * inv;
        float s, c;
        sincosf(ang, &s, &c);
        g_cos[i] = c;
        g_sin[i] = s;
    }
}

// ---------------------------------------------------------------------------
// RoPE on q (scaled by log2e/sqrt(96)) and k, on fp16 hi/lo planes
// ---------------------------------------------------------------------------
__global__ __launch_bounds__(256) void rope_kernel() {
    const float SC2 = 1.4426950408889634f * 0.10206207261596575f;
    int tok = blockIdx.x;
    int t  = (tok >> 8) & 31;
    int s  = tok & 255;
    int rh = s >> 4, cw = s & 15;
    __half* ph = g_qkvh + (size_t)tok * QKVD;
    __half* pl = g_qkvl + (size_t)tok * QKVD;
    for (int i = threadIdx.x; i < 960; i += 256) {
        int head = i / 48, p = i % 48;
        int chunk = p >> 4, j = p & 15;
        int col0 = (head < 16 ? head * 96 : 1536 + (head - 16) * 96) + chunk * 32 + j;
        int pos = (chunk == 0) ? t : (chunk == 1 ? 32 + rh : 48 + cw);
        float c = g_cos[pos * 16 + j], sn = g_sin[pos * 16 + j];
        float x1 = __half2float(ph[col0])      + __half2float(pl[col0]);
        float x2 = __half2float(ph[col0 + 16]) + __half2float(pl[col0 + 16]);
        float y1 = x1 * c - x2 * sn;
        float y2 = x2 * c + x1 * sn;
        if (head < 16) { y1 *= SC2; y2 *= SC2; }
        __half h1 = __float2half_rn(y1);
        __half h2 = __float2half_rn(y2);
        ph[col0]      = h1;  pl[col0]      = __float2half_rn(y1 - __half2float(h1));
        ph[col0 + 16] = h2;  pl[col0 + 16] = __float2half_rn(y2 - __half2float(h2));
    }
}

// ---------------------------------------------------------------------------
// FP16x2 GEMM (qkv proj): C = Ah*Bh + Ah*Bl, split fp16 output planes.
// 128x128 tile, BK=32, 8 warps, warp tile 64x32, m16n8k16, reg-prefetch.
// ---------------------------------------------------------------------------
__global__ __launch_bounds__(256) void gemm_x2(
    const __half* __restrict__ Ah,
    const __half* __restrict__ Bh, const __half* __restrict__ Bl,
    __half* __restrict__ Ch, __half* __restrict__ Cl,
    int M, int N, int K)
{
    __shared__ __half sAh[128 * 40], sBh[128 * 40], sBl[128 * 40];

    const int tid = threadIdx.x, warp = tid >> 5, lane = tid & 31;
    const int g = lane >> 2, tg = lane & 3;
    const int m0 = blockIdx.y * 128, n0 = blockIdx.x * 128;
    const int wm = (warp >> 2) * 64, wn = (warp & 3) * 32;
    const int lrow = tid >> 1, lcol = (tid & 1) * 16;

    float acc[4][4][4];
    #pragma unroll
    for (int i = 0; i < 4; i++)
        #pragma unroll
        for (int j = 0; j < 4; j++)
            #pragma unroll
            for (int e = 0; e < 4; e++) acc[i][j][e] = 0.f;

    const __half* gAh = Ah + (size_t)(m0 + lrow) * K + lcol;
    const __half* gBh = Bh + (size_t)(n0 + lrow) * K + lcol;
    const __half* gBl = Bl + (size_t)(n0 + lrow) * K + lcol;

    uint4 pah[2], pbh[2], pbl[2];
    #define LD8(kt) do { \
        pah[0] = *(const uint4*)(gAh + (kt));     pah[1] = *(const uint4*)(gAh + (kt) + 8); \
        pbh[0] = *(const uint4*)(gBh + (kt));     pbh[1] = *(const uint4*)(gBh + (kt) + 8); \
        pbl[0] = *(const uint4*)(gBl + (kt));     pbl[1] = *(const uint4*)(gBl + (kt) + 8); \
    } while (0)

    LD8(0);

    const uint32_t* A32h = (const uint32_t*)sAh;
    const uint32_t* B32h = (const uint32_t*)sBh;
    const uint32_t* B32l = (const uint32_t*)sBl;

    for (int kt = 0; kt < K; kt += 32) {
        *(uint4*)(sAh + lrow * 40 + lcol) = pah[0]; *(uint4*)(sAh + lrow * 40 + lcol + 8) = pah[1];
        *(uint4*)(sBh + lrow * 40 + lcol) = pbh[0]; *(uint4*)(sBh + lrow * 40 + lcol + 8) = pbh[1];
        *(uint4*)(sBl + lrow * 40 + lcol) = pbl[0]; *(uint4*)(sBl + lrow * 40 + lcol + 8) = pbl[1];
        __syncthreads();
        if (kt + 32 < K) LD8(kt + 32);

        #pragma unroll
        for (int ks = 0; ks < 2; ks++) {
            uint32_t fah[4][4];
            #pragma unroll
            for (int i = 0; i < 4; i++) {
                int r = (wm + i * 16 + g) * 20 + ks * 8 + tg;
                int r8 = r + 160;
                fah[i][0] = A32h[r]; fah[i][1] = A32h[r8]; fah[i][2] = A32h[r + 4]; fah[i][3] = A32h[r8 + 4];
            }
            #pragma unroll
            for (int j = 0; j < 4; j++) {
                int nb = (wn + j * 8 + g) * 20 + ks * 8 + tg;
                uint32_t bh0 = B32h[nb], bh1 = B32h[nb + 4];
                uint32_t bl0 = B32l[nb], bl1 = B32l[nb + 4];
                #pragma unroll
                for (int i = 0; i < 4; i++) {
                    mma_f16(acc[i][j], fah[i][0], fah[i][1], fah[i][2], fah[i][3], bh0, bh1);
                    mma_f16(acc[i][j], fah[i][0], fah[i][1], fah[i][2], fah[i][3], bl0, bl1);
                }
            }
        }
        __syncthreads();
    }
    #undef LD8

    #pragma unroll
    for (int i = 0; i < 4; i++)
        #pragma unroll
        for (int j = 0; j < 4; j++) {
            int row = m0 + wm + i * 16 + g;
            int col = n0 + wn + j * 8 + 2 * tg;
            uint32_t h0, l0, h1, l1;
            split2h(acc[i][j][0], acc[i][j][1], h0, l0);
            split2h(acc[i][j][2], acc[i][j][3], h1, l1);
            *(uint32_t*)(Ch + (size_t)row * N + col)       = h0;
            *(uint32_t*)(Cl + (size_t)row * N + col)       = l0;
            *(uint32_t*)(Ch + (size_t)(row + 8) * N + col) = h1;
            *(uint32_t*)(Cl + (size_t)(row + 8) * N + col) = l1;
        }
}

// ---------------------------------------------------------------------------
// Plain FP16 GEMM (o-proj): C = Ah*Bh, fp32 output. Half the MMA count.
// Same tiling as gemm_x2.
// ---------------------------------------------------------------------------
__global__ __launch_bounds__(256) void gemm_x1(
    const __half* __restrict__ Ah,
    const __half* __restrict__ Bh,
    float* __restrict__ C,
    int M, int N, int K)
{
    __shared__ __half sAh[128 * 40], sBh[128 * 40];

    const int tid = threadIdx.x, warp = tid >> 5, lane = tid & 31;
    const int g = lane >> 2, tg = lane & 3;
    const int m0 = blockIdx.y * 128, n0 = blockIdx.x * 128;
    const int wm = (warp >> 2) * 64, wn = (warp & 3) * 32;
    const int lrow = tid >> 1, lcol = (tid & 1) * 16;

    float acc[4][4][4];
    #pragma unroll
    for (int i = 0; i < 4; i++)
        #pragma unroll
        for (int j = 0; j < 4; j++)
            #pragma unroll
            for (int e = 0; e < 4; e++) acc[i][j][e] = 0.f;

    const __half* gAh = Ah + (size_t)(m0 + lrow) * K + lcol;
    const __half* gBh = Bh + (size_t)(n0 + lrow) * K + lcol;

    uint4 pah[2], pbh[2];
    #define LD8(kt) do { \
        pah[0] = *(const uint4*)(gAh + (kt));     pah[1] = *(const uint4*)(gAh + (kt) + 8); \
        pbh[0] = *(const uint4*)(gBh + (kt));     pbh[1] = *(const uint4*)(gBh + (kt) + 8); \
    } while (0)

    LD8(0);

    const uint32_t* A32h = (const uint32_t*)sAh;
    const uint32_t* B32h = (const uint32_t*)sBh;

    for (int kt = 0; kt < K; kt += 32) {
        *(uint4*)(sAh + lrow * 40 + lcol) = pah[0]; *(uint4*)(sAh + lrow * 40 + lcol + 8) = pah[1];
        *(uint4*)(sBh + lrow * 40 + lcol) = pbh[0]; *(uint4*)(sBh + lrow * 40 + lcol + 8) = pbh[1];
        __syncthreads();
        if (kt + 32 < K) LD8(kt + 32);

        #pragma unroll
        for (int ks = 0; ks < 2; ks++) {
            uint32_t fah[4][4];
            #pragma unroll
            for (int i = 0; i < 4; i++) {
                int r = (wm + i * 16 + g) * 20 + ks * 8 + tg;
                int r8 = r + 160;
                fah[i][0] = A32h[r]; fah[i][1] = A32h[r8]; fah[i][2] = A32h[r + 4]; fah[i][3] = A32h[r8 + 4];
            }
            #pragma unroll
            for (int j = 0; j < 4; j++) {
                int nb = (wn + j * 8 + g) * 20 + ks * 8 + tg;
                uint32_t bh0 = B32h[nb], bh1 = B32h[nb + 4];
                #pragma unroll
                for (int i = 0; i < 4; i++)
                    mma_f16(acc[i][j], fah[i][0], fah[i][1], fah[i][2], fah[i][3], bh0, bh1);
            }
        }
        __syncthreads();
    }
    #undef LD8

    #pragma unroll
    for (int i = 0; i < 4; i++)
        #pragma unroll
        for (int j = 0; j < 4; j++) {
            int row = m0 + wm + i * 16 + g;
            int col = n0 + wn + j * 8 + 2 * tg;
            *(float2*)(C + (size_t)row * N + col)       = make_float2(acc[i][j][0], acc[i][j][1]);
            *(float2*)(C + (size_t)(row + 8) * N + col) = make_float2(acc[i][j][2], acc[i][j][3]);
        }
}

// ---------------------------------------------------------------------------
// Attention: CTA = (b,t,head,64-query tile), 128 threads (4 warps x 16 rows).
// Flash-style, no-max f32 ex2 softmax, fp16 x2 matmuls:
//   scores ~= Qh*Kh + Qh*Kl ;  out ~= Ph*Vh + Ph*Vl.
// ---------------------------------------------------------------------------
__global__ __launch_bounds__(128) void attn_kernel() {
    extern __shared__ __half smb[];
    __half* Qh = smb;                 // [64][120]
    __half* Kh = Qh + 7680;           // [64][120]
    __half* Kl = Kh + 7680;
    __half* Vh = Kl + 7680;           // transposed [96][72]
    __half* Vl = Vh + 6912;

    const int tid = threadIdx.x, warp = tid >> 5, lane = tid & 31;
    const int g = lane >> 2, tg = lane & 3;
    const int bid = blockIdx.x;
    const int qt = bid & 3, h = (bid >> 2) & 15, bt = bid >> 6, grp = h >> 2;
    const size_t tokbase = (size_t)bt * 256;

    #pragma unroll
    for (int t = 0; t < 6; t++) {
        int u = tid + t * 128;
        int row = u / 12, c8 = u % 12;
        size_t gb = (tokbase + qt * 64 + row) * QKVD + h * 96 + c8 * 8;
        *(uint4*)(Qh + row * 120 + c8 * 8) = *(const uint4*)(g_qkvh + gb);
    }

    const uint32_t* Q32h = (const uint32_t*)Qh;
    const uint32_t* K32h = (const uint32_t*)Kh;
    const uint32_t* K32l = (const uint32_t*)Kl;
    const uint32_t* V32h = (const uint32_t*)Vh;
    const uint32_t* V32l = (const uint32_t*)Vl;

    float acc[12][4];
    #pragma unroll
    for (int j = 0; j < 12; j++)
        #pragma unroll
        for (int e = 0; e < 4; e++) acc[j][e] = 0.f;
    float rs0 = 0.f, rs1 = 0.f;

    for (int c = 0; c < 4; c++) {
        #pragma unroll
        for (int t = 0; t < 6; t++) {
            int u = tid + t * 128;
            int row = u / 12, c8 = u % 12;
            size_t gb = (tokbase + c * 64 + row) * QKVD + 1536 + grp * 96 + c8 * 8;
            *(uint4*)(Kh + row * 120 + c8 * 8) = *(const uint4*)(g_qkvh + gb);
            *(uint4*)(Kl + row * 120 + c8 * 8) = *(const uint4*)(g_qkvl + gb);
        }
        #pragma unroll
        for (int t = 0; t < 24; t++) {
            int u = tid + t * 128;
            int key = u / 48, d = (u % 48) * 2;
            size_t gb = (tokbase + c * 64 + key) * QKVD + 1920 + grp * 96 + d;
            __half2 ph = *(const __half2*)(g_qkvh + gb);
            __half2 pl = *(const __half2*)(g_qkvl + gb);
            Vh[d * 72 + key] = __low2half(ph);  Vh[(d + 1) * 72 + key] = __high2half(ph);
            Vl[d * 72 + key] = __low2half(pl);  Vl[(d + 1) * 72 + key] = __high2half(pl);
        }
        __syncthreads();

        float s[8][4];
        #pragma unroll
        for (int j = 0; j < 8; j++)
            #pragma unroll
            for (int e = 0; e < 4; e++) s[j][e] = 0.f;

        #pragma unroll
        for (int ks = 0; ks < 6; ks++) {
            int r = (warp * 16 + g) * 60 + ks * 8 + tg;
            int r8 = r + 480;
            uint32_t a0 = Q32h[r], a1 = Q32h[r8], a2 = Q32h[r + 4], a3 = Q32h[r8 + 4];
            #pragma unroll
            for (int j = 0; j < 8; j++) {
                int nb = (j * 8 + g) * 60 + ks * 8 + tg;
                uint32_t bh0 = K32h[nb], bh1 = K32h[nb + 4];
                uint32_t bl0 = K32l[nb], bl1 = K32l[nb + 4];
                mma_f16(s[j], a0, a1, a2, a3, bh0, bh1);
                mma_f16(s[j], a0, a1, a2, a3, bl0, bl1);
            }
        }

        #pragma unroll
        for (int j = 0; j < 8; j++) {
            s[j][0] = ex2f(s[j][0]); s[j][1] = ex2f(s[j][1]);
            s[j][2] = ex2f(s[j][2]); s[j][3] = ex2f(s[j][3]);
            rs0 += s[j][0] + s[j][1];
            rs1 += s[j][2] + s[j][3];
        }

        #pragma unroll
        for (int kk = 0; kk < 4; kk++) {
            uint32_t A0 = packh2(s[2 * kk][0],     s[2 * kk][1]);
            uint32_t A1 = packh2(s[2 * kk][2],     s[2 * kk][3]);
            uint32_t A2 = packh2(s[2 * kk + 1][0], s[2 * kk + 1][1]);
            uint32_t A3 = packh2(s[2 * kk + 1][2], s[2 * kk + 1][3]);
            #pragma unroll
            for (int j = 0; j < 12; j++) {
                int vb = (j * 8 + g) * 36 + kk * 8 + tg;
                uint32_t bh0 = V32h[vb], bh1 = V32h[vb + 4];
                uint32_t bl0 = V32l[vb], bl1 = V32l[vb + 4];
                mma_f16(acc[j], A0, A1, A2, A3, bh0, bh1);
                mma_f16(acc[j], A0, A1, A2, A3, bl0, bl1);
            }
        }
        __syncthreads();
    }

    rs0 += __shfl_xor_sync(0xffffffffu, rs0, 1);
    rs0 += __shfl_xor_sync(0xffffffffu, rs0, 2);
    rs1 += __shfl_xor_sync(0xffffffffu, rs1, 1);
    rs1 += __shfl_xor_sync(0xffffffffu, rs1, 2);
    float i0 = 1.f / rs0, i1 = 1.f / rs1;

    int tok0 = bt * 256 + qt * 64 + warp * 16 + g;
    #pragma unroll
    for (int j = 0; j < 12; j++) {
        int col = h * 96 + j * 8 + 2 * tg;
        *(uint32_t*)(g_ath + (size_t)tok0 * DM + col)       = packh2(acc[j][0] * i0, acc[j][1] * i0);
        *(uint32_t*)(g_ath + (size_t)(tok0 + 8) * DM + col) = packh2(acc[j][2] * i1, acc[j][3] * i1);
    }
}

// ---------------------------------------------------------------------------
extern "C" void kernel_launch(void* const* d_in, const int* in_sizes, int n_in,
                              void* d_out, int out_size) {
    (void)in_sizes; (void)n_in; (void)out_size;
    const float* x     = (const float*)d_in[0];
    const float* w_qkv = (const float*)d_in[2];
    const float* w_o   = (const float*)d_in[3];
    float* out = (float*)d_out;

    __half *xh, *wqh, *wql, *woh, *qkvh, *qkvl, *ath;
    cudaGetSymbolAddress((void**)&xh, g_xh);
    cudaGetSymbolAddress((void**)&wqh, g_wqh);   cudaGetSymbolAddress((void**)&wql, g_wql);
    cudaGetSymbolAddress((void**)&woh, g_woh);
    cudaGetSymbolAddress((void**)&qkvh, g_qkvh); cudaGetSymbolAddress((void**)&qkvl, g_qkvl);
    cudaGetSymbolAddress((void**)&ath, g_ath);

    cudaFuncSetAttribute(attn_kernel, cudaFuncAttributeMaxDynamicSharedMemorySize, 73728);

    rope_table_kernel<<<1, 1024>>>();
    cvt_kernel<<<24576, 256>>>((const float4*)x,   (uint32_t*)xh,  6291456);
    cvt_kernel<<<2304,  256>>>((const float4*)w_o, (uint32_t*)woh, 589824);
    split_kernel<<<3456, 256>>>((const float4*)w_qkv, (uint32_t*)wqh, (uint32_t*)wql, 884736);

    dim3 g1(QKVD / 128, NTOK / 128);
    gemm_x2<<<g1, 256>>>(xh, wqh, wql, qkvh, qkvl, NTOK, QKVD, DM);

    rope_kernel<<<NTOK, 256>>>();

    attn_kernel<<<4096, 128, 73728>>>();

    dim3 g2(DM / 128, NTOK / 128);
    gemm_x1<<<g2, 256>>>(ath, woh, out, NTOK, DM, DM);
}

// round 11
// speedup vs baseline: 2.9547x; 1.4776x over previous
#include <cuda_runtime.h>
#include <cuda_bf16.h>
#include <cuda_fp16.h>
#include <cstdint>
#include <math.h>

#define NTOK  16384
#define DM    1536
#define QKVD  2304

// ---- scratch (__device__ globals; no allocations allowed) ----
__device__ __half g_xh[(size_t)NTOK * DM];
__device__ __half g_wqh[(size_t)QKVD * DM];
__device__ __half g_woh[(size_t)DM * DM];
__device__ __half g_qkvh[(size_t)NTOK * QKVD], g_qkvl[(size_t)NTOK * QKVD];
__device__ __half g_ath[(size_t)NTOK * DM];
__device__ float g_cos[1024], g_sin[1024];

// ---- helpers ----
__device__ __forceinline__ void split2h(float x, float y, uint32_t& hi, uint32_t& lo) {
    __half hx = __float2half_rn(x), hy = __float2half_rn(y);
    __half lx = __float2half_rn(x - __half2float(hx));
    __half ly = __float2half_rn(y - __half2float(hy));
    __half2 H = __halves2half2(hx, hy), L = __halves2half2(lx, ly);
    hi = *reinterpret_cast<uint32_t*>(&H);
    lo = *reinterpret_cast<uint32_t*>(&L);
}

__device__ __forceinline__ uint32_t packh2(float x, float y) {
    __half2 t = __floats2half2_rn(x, y);
    return *reinterpret_cast<uint32_t*>(&t);
}

__device__ __forceinline__ void mma_f16(float* c, uint32_t a0, uint32_t a1, uint32_t a2, uint32_t a3,
                                        uint32_t b0, uint32_t b1) {
    asm volatile(
        "mma.sync.aligned.m16n8k16.row.col.f32.f16.f16.f32 "
        "{%0,%1,%2,%3},{%4,%5,%6,%7},{%8,%9},{%0,%1,%2,%3};\n"
        : "+f"(c[0]), "+f"(c[1]), "+f"(c[2]), "+f"(c[3])
        : "r"(a0), "r"(a1), "r"(a2), "r"(a3), "r"(b0), "r"(b1));
}

__device__ __forceinline__ float ex2f(float x) {
    float r;
    asm("ex2.approx.ftz.f32 %0, %1;" : "=f"(r) : "f"(x));
    return r;
}

// ---------------------------------------------------------------------------
// fp32 -> fp16 hi-only convert
// ---------------------------------------------------------------------------
__global__ __launch_bounds__(256) void cvt_kernel(const float4* __restrict__ src,
                                                  uint32_t* __restrict__ h, int n4) {
    int i = blockIdx.x * 256 + threadIdx.x;
    if (i < n4) {
        float4 v = src[i];
        h[2 * i]     = packh2(v.x, v.y);
        h[2 * i + 1] = packh2(v.z, v.w);
    }
}

// ---------------------------------------------------------------------------
// RoPE tables
// ---------------------------------------------------------------------------
__global__ void rope_table_kernel() {
    int i = threadIdx.x;
    if (i < 1024) {
        int r = i >> 4, j = i & 15;
        int pos = (r < 32) ? r : (r < 48 ? r - 32 : r - 48);
        float inv = powf(10000.0f, -(float)j / 16.0f);
        float ang = (float)pos * inv;
        float s, c;
        sincosf(ang, &s, &c);
        g_cos[i] = c;
        g_sin[i] = s;
    }
}

// ---------------------------------------------------------------------------
// RoPE on q (scaled by log2e/sqrt(96)) and k, on fp16 hi/lo planes
// ---------------------------------------------------------------------------
__global__ __launch_bounds__(256) void rope_kernel() {
    const float SC2 = 1.4426950408889634f * 0.10206207261596575f;
    int tok = blockIdx.x;
    int t  = (tok >> 8) & 31;
    int s  = tok & 255;
    int rh = s >> 4, cw = s & 15;
    __half* ph = g_qkvh + (size_t)tok * QKVD;
    __half* pl = g_qkvl + (size_t)tok * QKVD;
    for (int i = threadIdx.x; i < 960; i += 256) {
        int head = i / 48, p = i % 48;
        int chunk = p >> 4, j = p & 15;
        int col0 = (head < 16 ? head * 96 : 1536 + (head - 16) * 96) + chunk * 32 + j;
        int pos = (chunk == 0) ? t : (chunk == 1 ? 32 + rh : 48 + cw);
        float c = g_cos[pos * 16 + j], sn = g_sin[pos * 16 + j];
        float x1 = __half2float(ph[col0])      + __half2float(pl[col0]);
        float x2 = __half2float(ph[col0 + 16]) + __half2float(pl[col0 + 16]);
        float y1 = x1 * c - x2 * sn;
        float y2 = x2 * c + x1 * sn;
        if (head < 16) { y1 *= SC2; y2 *= SC2; }
        __half h1 = __float2half_rn(y1);
        __half h2 = __float2half_rn(y2);
        ph[col0]      = h1;  pl[col0]      = __float2half_rn(y1 - __half2float(h1));
        ph[col0 + 16] = h2;  pl[col0 + 16] = __float2half_rn(y2 - __half2float(h2));
    }
}

// ---------------------------------------------------------------------------
// Plain FP16 GEMM: C = Ah*Bh. SPLIT_OUT=1 -> fp16 hi/lo planes; 0 -> fp32.
// 128x128 tile, BK=32, 8 warps, warp tile 64x32, m16n8k16, reg-prefetch.
// ---------------------------------------------------------------------------
template<int SPLIT_OUT>
__global__ __launch_bounds__(256) void gemm_h1(
    const __half* __restrict__ Ah,
    const __half* __restrict__ Bh,
    float* __restrict__ C, __half* __restrict__ Ch, __half* __restrict__ Cl,
    int M, int N, int K)
{
    __shared__ __half sAh[128 * 40], sBh[128 * 40];

    const int tid = threadIdx.x, warp = tid >> 5, lane = tid & 31;
    const int g = lane >> 2, tg = lane & 3;
    const int m0 = blockIdx.y * 128, n0 = blockIdx.x * 128;
    const int wm = (warp >> 2) * 64, wn = (warp & 3) * 32;
    const int lrow = tid >> 1, lcol = (tid & 1) * 16;

    float acc[4][4][4];
    #pragma unroll
    for (int i = 0; i < 4; i++)
        #pragma unroll
        for (int j = 0; j < 4; j++)
            #pragma unroll
            for (int e = 0; e < 4; e++) acc[i][j][e] = 0.f;

    const __half* gAh = Ah + (size_t)(m0 + lrow) * K + lcol;
    const __half* gBh = Bh + (size_t)(n0 + lrow) * K + lcol;

    uint4 pah[2], pbh[2];
    #define LD8(kt) do { \
        pah[0] = *(const uint4*)(gAh + (kt));     pah[1] = *(const uint4*)(gAh + (kt) + 8); \
        pbh[0] = *(const uint4*)(gBh + (kt));     pbh[1] = *(const uint4*)(gBh + (kt) + 8); \
    } while (0)

    LD8(0);

    const uint32_t* A32h = (const uint32_t*)sAh;
    const uint32_t* B32h = (const uint32_t*)sBh;

    for (int kt = 0; kt < K; kt += 32) {
        *(uint4*)(sAh + lrow * 40 + lcol) = pah[0]; *(uint4*)(sAh + lrow * 40 + lcol + 8) = pah[1];
        *(uint4*)(sBh + lrow * 40 + lcol) = pbh[0]; *(uint4*)(sBh + lrow * 40 + lcol + 8) = pbh[1];
        __syncthreads();
        if (kt + 32 < K) LD8(kt + 32);

        #pragma unroll
        for (int ks = 0; ks < 2; ks++) {
            uint32_t fah[4][4];
            #pragma unroll
            for (int i = 0; i < 4; i++) {
                int r = (wm + i * 16 + g) * 20 + ks * 8 + tg;
                int r8 = r + 160;
                fah[i][0] = A32h[r]; fah[i][1] = A32h[r8]; fah[i][2] = A32h[r + 4]; fah[i][3] = A32h[r8 + 4];
            }
            #pragma unroll
            for (int j = 0; j < 4; j++) {
                int nb = (wn + j * 8 + g) * 20 + ks * 8 + tg;
                uint32_t bh0 = B32h[nb], bh1 = B32h[nb + 4];
                #pragma unroll
                for (int i = 0; i < 4; i++)
                    mma_f16(acc[i][j], fah[i][0], fah[i][1], fah[i][2], fah[i][3], bh0, bh1);
            }
        }
        __syncthreads();
    }
    #undef LD8

    #pragma unroll
    for (int i = 0; i < 4; i++)
        #pragma unroll
        for (int j = 0; j < 4; j++) {
            int row = m0 + wm + i * 16 + g;
            int col = n0 + wn + j * 8 + 2 * tg;
            if (SPLIT_OUT) {
                uint32_t h0, l0, h1, l1;
                split2h(acc[i][j][0], acc[i][j][1], h0, l0);
                split2h(acc[i][j][2], acc[i][j][3], h1, l1);
                *(uint32_t*)(Ch + (size_t)row * N + col)       = h0;
                *(uint32_t*)(Cl + (size_t)row * N + col)       = l0;
                *(uint32_t*)(Ch + (size_t)(row + 8) * N + col) = h1;
                *(uint32_t*)(Cl + (size_t)(row + 8) * N + col) = l1;
            } else {
                *(float2*)(C + (size_t)row * N + col)       = make_float2(acc[i][j][0], acc[i][j][1]);
                *(float2*)(C + (size_t)(row + 8) * N + col) = make_float2(acc[i][j][2], acc[i][j][3]);
            }
        }
}

// ---------------------------------------------------------------------------
// Attention: CTA = (b,t,head,64-query tile), 128 threads (4 warps x 16 rows).
// Flash-style, no-max f32 ex2 softmax.
//   scores ~= Qh*Kh + Qh*Kl (x2: softmax-sensitive) ;  out ~= Ph*Vh (x1).
// ---------------------------------------------------------------------------
__global__ __launch_bounds__(128) void attn_kernel() {
    extern __shared__ __half smb[];
    __half* Qh = smb;                 // [64][120]
    __half* Kh = Qh + 7680;           // [64][120]
    __half* Kl = Kh + 7680;
    __half* Vh = Kl + 7680;           // transposed [96][72]

    const int tid = threadIdx.x, warp = tid >> 5, lane = tid & 31;
    const int g = lane >> 2, tg = lane & 3;
    const int bid = blockIdx.x;
    const int qt = bid & 3, h = (bid >> 2) & 15, bt = bid >> 6, grp = h >> 2;
    const size_t tokbase = (size_t)bt * 256;

    #pragma unroll
    for (int t = 0; t < 6; t++) {
        int u = tid + t * 128;
        int row = u / 12, c8 = u % 12;
        size_t gb = (tokbase + qt * 64 + row) * QKVD + h * 96 + c8 * 8;
        *(uint4*)(Qh + row * 120 + c8 * 8) = *(const uint4*)(g_qkvh + gb);
    }

    const uint32_t* Q32h = (const uint32_t*)Qh;
    const uint32_t* K32h = (const uint32_t*)Kh;
    const uint32_t* K32l = (const uint32_t*)Kl;
    const uint32_t* V32h = (const uint32_t*)Vh;

    float acc[12][4];
    #pragma unroll
    for (int j = 0; j < 12; j++)
        #pragma unroll
        for (int e = 0; e < 4; e++) acc[j][e] = 0.f;
    float rs0 = 0.f, rs1 = 0.f;

    for (int c = 0; c < 4; c++) {
        #pragma unroll
        for (int t = 0; t < 6; t++) {
            int u = tid + t * 128;
            int row = u / 12, c8 = u % 12;
            size_t gb = (tokbase + c * 64 + row) * QKVD + 1536 + grp * 96 + c8 * 8;
            *(uint4*)(Kh + row * 120 + c8 * 8) = *(const uint4*)(g_qkvh + gb);
            *(uint4*)(Kl + row * 120 + c8 * 8) = *(const uint4*)(g_qkvl + gb);
        }
        #pragma unroll
        for (int t = 0; t < 24; t++) {
            int u = tid + t * 128;
            int key = u / 48, d = (u % 48) * 2;
            size_t gb = (tokbase + c * 64 + key) * QKVD + 1920 + grp * 96 + d;
            __half2 ph = *(const __half2*)(g_qkvh + gb);
            Vh[d * 72 + key] = __low2half(ph);  Vh[(d + 1) * 72 + key] = __high2half(ph);
        }
        __syncthreads();

        float s[8][4];
        #pragma unroll
        for (int j = 0; j < 8; j++)
            #pragma unroll
            for (int e = 0; e < 4; e++) s[j][e] = 0.f;

        #pragma unroll
        for (int ks = 0; ks < 6; ks++) {
            int r = (warp * 16 + g) * 60 + ks * 8 + tg;
            int r8 = r + 480;
            uint32_t a0 = Q32h[r], a1 = Q32h[r8], a2 = Q32h[r + 4], a3 = Q32h[r8 + 4];
            #pragma unroll
            for (int j = 0; j < 8; j++) {
                int nb = (j * 8 + g) * 60 + ks * 8 + tg;
                uint32_t bh0 = K32h[nb], bh1 = K32h[nb + 4];
                uint32_t bl0 = K32l[nb], bl1 = K32l[nb + 4];
                mma_f16(s[j], a0, a1, a2, a3, bh0, bh1);
                mma_f16(s[j], a0, a1, a2, a3, bl0, bl1);
            }
        }

        #pragma unroll
        for (int j = 0; j < 8; j++) {
            s[j][0] = ex2f(s[j][0]); s[j][1] = ex2f(s[j][1]);
            s[j][2] = ex2f(s[j][2]); s[j][3] = ex2f(s[j][3]);
            rs0 += s[j][0] + s[j][1];
            rs1 += s[j][2] + s[j][3];
        }

        #pragma unroll
        for (int kk = 0; kk < 4; kk++) {
            uint32_t A0 = packh2(s[2 * kk][0],     s[2 * kk][1]);
            uint32_t A1 = packh2(s[2 * kk][2],     s[2 * kk][3]);
            uint32_t A2 = packh2(s[2 * kk + 1][0], s[2 * kk + 1][1]);
            uint32_t A3 = packh2(s[2 * kk + 1][2], s[2 * kk + 1][3]);
            #pragma unroll
            for (int j = 0; j < 12; j++) {
                int vb = (j * 8 + g) * 36 + kk * 8 + tg;
                uint32_t bh0 = V32h[vb], bh1 = V32h[vb + 4];
                mma_f16(acc[j], A0, A1, A2, A3, bh0, bh1);
            }
        }
        __syncthreads();
    }

    rs0 += __shfl_xor_sync(0xffffffffu, rs0, 1);
    rs0 += __shfl_xor_sync(0xffffffffu, rs0, 2);
    rs1 += __shfl_xor_sync(0xffffffffu, rs1, 1);
    rs1 += __shfl_xor_sync(0xffffffffu, rs1, 2);
    float i0 = 1.f / rs0, i1 = 1.f / rs1;

    int tok0 = bt * 256 + qt * 64 + warp * 16 + g;
    #pragma unroll
    for (int j = 0; j < 12; j++) {
        int col = h * 96 + j * 8 + 2 * tg;
        *(uint32_t*)(g_ath + (size_t)tok0 * DM + col)       = packh2(acc[j][0] * i0, acc[j][1] * i0);
        *(uint32_t*)(g_ath + (size_t)(tok0 + 8) * DM + col) = packh2(acc[j][2] * i1, acc[j][3] * i1);
    }
}

// ---------------------------------------------------------------------------
extern "C" void kernel_launch(void* const* d_in, const int* in_sizes, int n_in,
                              void* d_out, int out_size) {
    (void)in_sizes; (void)n_in; (void)out_size;
    const float* x     = (const float*)d_in[0];
    const float* w_qkv = (const float*)d_in[2];
    const float* w_o   = (const float*)d_in[3];
    float* out = (float*)d_out;

    __half *xh, *wqh, *woh, *qkvh, *qkvl, *ath;
    cudaGetSymbolAddress((void**)&xh, g_xh);
    cudaGetSymbolAddress((void**)&wqh, g_wqh);
    cudaGetSymbolAddress((void**)&woh, g_woh);
    cudaGetSymbolAddress((void**)&qkvh, g_qkvh); cudaGetSymbolAddress((void**)&qkvl, g_qkvl);
    cudaGetSymbolAddress((void**)&ath, g_ath);

    cudaFuncSetAttribute(attn_kernel, cudaFuncAttributeMaxDynamicSharedMemorySize, 59904);

    rope_table_kernel<<<1, 1024>>>();
    cvt_kernel<<<24576, 256>>>((const float4*)x,     (uint32_t*)xh,  6291456);
    cvt_kernel<<<3456,  256>>>((const float4*)w_qkv, (uint32_t*)wqh, 884736);
    cvt_kernel<<<2304,  256>>>((const float4*)w_o,   (uint32_t*)woh, 589824);

    dim3 g1(QKVD / 128, NTOK / 128);
    gemm_h1<1><<<g1, 256>>>(xh, wqh, nullptr, qkvh, qkvl, NTOK, QKVD, DM);

    rope_kernel<<<NTOK, 256>>>();

    attn_kernel<<<4096, 128, 59904>>>();

    dim3 g2(DM / 128, NTOK / 128);
    gemm_h1<0><<<g2, 256>>>(ath, woh, out, nullptr, nullptr, NTOK, DM, DM);
}

// round 12
// speedup vs baseline: 3.1603x; 1.0696x over previous
#include <cuda_runtime.h>
#include <cuda_bf16.h>
#include <cuda_fp16.h>
#include <cstdint>
#include <math.h>

#define NTOK  16384
#define DM    1536
#define QKVD  2304

// ---- scratch (__device__ globals; no allocations allowed) ----
__device__ __half g_xh[(size_t)NTOK * DM];
__device__ __half g_wqh[(size_t)QKVD * DM];
__device__ __half g_woh[(size_t)DM * DM];
__device__ __half g_qkvh[(size_t)NTOK * QKVD];
__device__ __half g_ath[(size_t)NTOK * DM];
__device__ float g_cos[1024], g_sin[1024];

// ---- helpers ----
__device__ __forceinline__ uint32_t packh2(float x, float y) {
    __half2 t = __floats2half2_rn(x, y);
    return *reinterpret_cast<uint32_t*>(&t);
}

__device__ __forceinline__ void mma_f16(float* c, uint32_t a0, uint32_t a1, uint32_t a2, uint32_t a3,
                                        uint32_t b0, uint32_t b1) {
    asm volatile(
        "mma.sync.aligned.m16n8k16.row.col.f32.f16.f16.f32 "
        "{%0,%1,%2,%3},{%4,%5,%6,%7},{%8,%9},{%0,%1,%2,%3};\n"
        : "+f"(c[0]), "+f"(c[1]), "+f"(c[2]), "+f"(c[3])
        : "r"(a0), "r"(a1), "r"(a2), "r"(a3), "r"(b0), "r"(b1));
}

__device__ __forceinline__ float ex2f(float x) {
    float r;
    asm("ex2.approx.ftz.f32 %0, %1;" : "=f"(r) : "f"(x));
    return r;
}

// ---------------------------------------------------------------------------
// fp32 -> fp16 convert
// ---------------------------------------------------------------------------
__global__ __launch_bounds__(256) void cvt_kernel(const float4* __restrict__ src,
                                                  uint32_t* __restrict__ h, int n4) {
    int i = blockIdx.x * 256 + threadIdx.x;
    if (i < n4) {
        float4 v = src[i];
        h[2 * i]     = packh2(v.x, v.y);
        h[2 * i + 1] = packh2(v.z, v.w);
    }
}

// ---------------------------------------------------------------------------
// RoPE tables
// ---------------------------------------------------------------------------
__global__ void rope_table_kernel() {
    int i = threadIdx.x;
    if (i < 1024) {
        int r = i >> 4, j = i & 15;
        int pos = (r < 32) ? r : (r < 48 ? r - 32 : r - 48);
        float inv = powf(10000.0f, -(float)j / 16.0f);
        float ang = (float)pos * inv;
        float s, c;
        sincosf(ang, &s, &c);
        g_cos[i] = c;
        g_sin[i] = s;
    }
}

// ---------------------------------------------------------------------------
// RoPE on q (scaled by log2e/sqrt(96)) and k, single fp16 plane
// ---------------------------------------------------------------------------
__global__ __launch_bounds__(256) void rope_kernel() {
    const float SC2 = 1.4426950408889634f * 0.10206207261596575f;
    int tok = blockIdx.x;
    int t  = (tok >> 8) & 31;
    int s  = tok & 255;
    int rh = s >> 4, cw = s & 15;
    __half* ph = g_qkvh + (size_t)tok * QKVD;
    for (int i = threadIdx.x; i < 960; i += 256) {
        int head = i / 48, p = i % 48;
        int chunk = p >> 4, j = p & 15;
        int col0 = (head < 16 ? head * 96 : 1536 + (head - 16) * 96) + chunk * 32 + j;
        int pos = (chunk == 0) ? t : (chunk == 1 ? 32 + rh : 48 + cw);
        float c = g_cos[pos * 16 + j], sn = g_sin[pos * 16 + j];
        float x1 = __half2float(ph[col0]);
        float x2 = __half2float(ph[col0 + 16]);
        float y1 = x1 * c - x2 * sn;
        float y2 = x2 * c + x1 * sn;
        if (head < 16) { y1 *= SC2; y2 *= SC2; }
        ph[col0]      = __float2half_rn(y1);
        ph[col0 + 16] = __float2half_rn(y2);
    }
}

// ---------------------------------------------------------------------------
// Plain FP16 GEMM: C = Ah*Bh. OUT16=1 -> fp16 output; 0 -> fp32.
// 128x128 tile, BK=32, 8 warps, warp tile 64x32, m16n8k16, reg-prefetch.
// ---------------------------------------------------------------------------
template<int OUT16>
__global__ __launch_bounds__(256) void gemm_h1(
    const __half* __restrict__ Ah,
    const __half* __restrict__ Bh,
    float* __restrict__ C, __half* __restrict__ Ch,
    int M, int N, int K)
{
    __shared__ __half sAh[128 * 40], sBh[128 * 40];

    const int tid = threadIdx.x, warp = tid >> 5, lane = tid & 31;
    const int g = lane >> 2, tg = lane & 3;
    const int m0 = blockIdx.y * 128, n0 = blockIdx.x * 128;
    const int wm = (warp >> 2) * 64, wn = (warp & 3) * 32;
    const int lrow = tid >> 1, lcol = (tid & 1) * 16;

    float acc[4][4][4];
    #pragma unroll
    for (int i = 0; i < 4; i++)
        #pragma unroll
        for (int j = 0; j < 4; j++)
            #pragma unroll
            for (int e = 0; e < 4; e++) acc[i][j][e] = 0.f;

    const __half* gAh = Ah + (size_t)(m0 + lrow) * K + lcol;
    const __half* gBh = Bh + (size_t)(n0 + lrow) * K + lcol;

    uint4 pah[2], pbh[2];
    #define LD8(kt) do { \
        pah[0] = *(const uint4*)(gAh + (kt));     pah[1] = *(const uint4*)(gAh + (kt) + 8); \
        pbh[0] = *(const uint4*)(gBh + (kt));     pbh[1] = *(const uint4*)(gBh + (kt) + 8); \
    } while (0)

    LD8(0);

    const uint32_t* A32h = (const uint32_t*)sAh;
    const uint32_t* B32h = (const uint32_t*)sBh;

    for (int kt = 0; kt < K; kt += 32) {
        *(uint4*)(sAh + lrow * 40 + lcol) = pah[0]; *(uint4*)(sAh + lrow * 40 + lcol + 8) = pah[1];
        *(uint4*)(sBh + lrow * 40 + lcol) = pbh[0]; *(uint4*)(sBh + lrow * 40 + lcol + 8) = pbh[1];
        __syncthreads();
        if (kt + 32 < K) LD8(kt + 32);

        #pragma unroll
        for (int ks = 0; ks < 2; ks++) {
            uint32_t fah[4][4];
            #pragma unroll
            for (int i = 0; i < 4; i++) {
                int r = (wm + i * 16 + g) * 20 + ks * 8 + tg;
                int r8 = r + 160;
                fah[i][0] = A32h[r]; fah[i][1] = A32h[r8]; fah[i][2] = A32h[r + 4]; fah[i][3] = A32h[r8 + 4];
            }
            #pragma unroll
            for (int j = 0; j < 4; j++) {
                int nb = (wn + j * 8 + g) * 20 + ks * 8 + tg;
                uint32_t bh0 = B32h[nb], bh1 = B32h[nb + 4];
                #pragma unroll
                for (int i = 0; i < 4; i++)
                    mma_f16(acc[i][j], fah[i][0], fah[i][1], fah[i][2], fah[i][3], bh0, bh1);
            }
        }
        __syncthreads();
    }
    #undef LD8

    #pragma unroll
    for (int i = 0; i < 4; i++)
        #pragma unroll
        for (int j = 0; j < 4; j++) {
            int row = m0 + wm + i * 16 + g;
            int col = n0 + wn + j * 8 + 2 * tg;
            if (OUT16) {
                *(uint32_t*)(Ch + (size_t)row * N + col)       = packh2(acc[i][j][0], acc[i][j][1]);
                *(uint32_t*)(Ch + (size_t)(row + 8) * N + col) = packh2(acc[i][j][2], acc[i][j][3]);
            } else {
                *(float2*)(C + (size_t)row * N + col)       = make_float2(acc[i][j][0], acc[i][j][1]);
                *(float2*)(C + (size_t)(row + 8) * N + col) = make_float2(acc[i][j][2], acc[i][j][3]);
            }
        }
}

// ---------------------------------------------------------------------------
// Attention: CTA = (b,t,head,64-query tile), 128 threads (4 warps x 16 rows).
// Flash-style, no-max f32 ex2 softmax, pure fp16 matmuls (f32 accum):
//   scores = Qh*Kh ;  out = Ph*Vh.
// ---------------------------------------------------------------------------
__global__ __launch_bounds__(128) void attn_kernel() {
    extern __shared__ __half smb[];
    __half* Qh = smb;                 // [64][120]
    __half* Kh = Qh + 7680;           // [64][120]
    __half* Vh = Kh + 7680;           // transposed [96][72]

    const int tid = threadIdx.x, warp = tid >> 5, lane = tid & 31;
    const int g = lane >> 2, tg = lane & 3;
    const int bid = blockIdx.x;
    const int qt = bid & 3, h = (bid >> 2) & 15, bt = bid >> 6, grp = h >> 2;
    const size_t tokbase = (size_t)bt * 256;

    #pragma unroll
    for (int t = 0; t < 6; t++) {
        int u = tid + t * 128;
        int row = u / 12, c8 = u % 12;
        size_t gb = (tokbase + qt * 64 + row) * QKVD + h * 96 + c8 * 8;
        *(uint4*)(Qh + row * 120 + c8 * 8) = *(const uint4*)(g_qkvh + gb);
    }

    const uint32_t* Q32h = (const uint32_t*)Qh;
    const uint32_t* K32h = (const uint32_t*)Kh;
    const uint32_t* V32h = (const uint32_t*)Vh;

    float acc[12][4];
    #pragma unroll
    for (int j = 0; j < 12; j++)
        #pragma unroll
        for (int e = 0; e < 4; e++) acc[j][e] = 0.f;
    float rs0 = 0.f, rs1 = 0.f;

    for (int c = 0; c < 4; c++) {
        #pragma unroll
        for (int t = 0; t < 6; t++) {
            int u = tid + t * 128;
            int row = u / 12, c8 = u % 12;
            size_t gb = (tokbase + c * 64 + row) * QKVD + 1536 + grp * 96 + c8 * 8;
            *(uint4*)(Kh + row * 120 + c8 * 8) = *(const uint4*)(g_qkvh + gb);
        }
        #pragma unroll
        for (int t = 0; t < 24; t++) {
            int u = tid + t * 128;
            int key = u / 48, d = (u % 48) * 2;
            size_t gb = (tokbase + c * 64 + key) * QKVD + 1920 + grp * 96 + d;
            __half2 ph = *(const __half2*)(g_qkvh + gb);
            Vh[d * 72 + key] = __low2half(ph);  Vh[(d + 1) * 72 + key] = __high2half(ph);
        }
        __syncthreads();

        float s[8][4];
        #pragma unroll
        for (int j = 0; j < 8; j++)
            #pragma unroll
            for (int e = 0; e < 4; e++) s[j][e] = 0.f;

        #pragma unroll
        for (int ks = 0; ks < 6; ks++) {
            int r = (warp * 16 + g) * 60 + ks * 8 + tg;
            int r8 = r + 480;
            uint32_t a0 = Q32h[r], a1 = Q32h[r8], a2 = Q32h[r + 4], a3 = Q32h[r8 + 4];
            #pragma unroll
            for (int j = 0; j < 8; j++) {
                int nb = (j * 8 + g) * 60 + ks * 8 + tg;
                uint32_t bh0 = K32h[nb], bh1 = K32h[nb + 4];
                mma_f16(s[j], a0, a1, a2, a3, bh0, bh1);
            }
        }

        #pragma unroll
        for (int j = 0; j < 8; j++) {
            s[j][0] = ex2f(s[j][0]); s[j][1] = ex2f(s[j][1]);
            s[j][2] = ex2f(s[j][2]); s[j][3] = ex2f(s[j][3]);
            rs0 += s[j][0] + s[j][1];
            rs1 += s[j][2] + s[j][3];
        }

        #pragma unroll
        for (int kk = 0; kk < 4; kk++) {
            uint32_t A0 = packh2(s[2 * kk][0],     s[2 * kk][1]);
            uint32_t A1 = packh2(s[2 * kk][2],     s[2 * kk][3]);
            uint32_t A2 = packh2(s[2 * kk + 1][0], s[2 * kk + 1][1]);
            uint32_t A3 = packh2(s[2 * kk + 1][2], s[2 * kk + 1][3]);
            #pragma unroll
            for (int j = 0; j < 12; j++) {
                int vb = (j * 8 + g) * 36 + kk * 8 + tg;
                uint32_t bh0 = V32h[vb], bh1 = V32h[vb + 4];
                mma_f16(acc[j], A0, A1, A2, A3, bh0, bh1);
            }
        }
        __syncthreads();
    }

    rs0 += __shfl_xor_sync(0xffffffffu, rs0, 1);
    rs0 += __shfl_xor_sync(0xffffffffu, rs0, 2);
    rs1 += __shfl_xor_sync(0xffffffffu, rs1, 1);
    rs1 += __shfl_xor_sync(0xffffffffu, rs1, 2);
    float i0 = 1.f / rs0, i1 = 1.f / rs1;

    int tok0 = bt * 256 + qt * 64 + warp * 16 + g;
    #pragma unroll
    for (int j = 0; j < 12; j++) {
        int col = h * 96 + j * 8 + 2 * tg;
        *(uint32_t*)(g_ath + (size_t)tok0 * DM + col)       = packh2(acc[j][0] * i0, acc[j][1] * i0);
        *(uint32_t*)(g_ath + (size_t)(tok0 + 8) * DM + col) = packh2(acc[j][2] * i1, acc[j][3] * i1);
    }
}

// ---------------------------------------------------------------------------
extern "C" void kernel_launch(void* const* d_in, const int* in_sizes, int n_in,
                              void* d_out, int out_size) {
    (void)in_sizes; (void)n_in; (void)out_size;
    const float* x     = (const float*)d_in[0];
    const float* w_qkv = (const float*)d_in[2];
    const float* w_o   = (const float*)d_in[3];
    float* out = (float*)d_out;

    __half *xh, *wqh, *woh, *qkvh, *ath;
    cudaGetSymbolAddress((void**)&xh, g_xh);
    cudaGetSymbolAddress((void**)&wqh, g_wqh);
    cudaGetSymbolAddress((void**)&woh, g_woh);
    cudaGetSymbolAddress((void**)&qkvh, g_qkvh);
    cudaGetSymbolAddress((void**)&ath, g_ath);

    cudaFuncSetAttribute(attn_kernel, cudaFuncAttributeMaxDynamicSharedMemorySize, 44544);

    rope_table_kernel<<<1, 1024>>>();
    cvt_kernel<<<24576, 256>>>((const float4*)x,     (uint32_t*)xh,  6291456);
    cvt_kernel<<<3456,  256>>>((const float4*)w_qkv, (uint32_t*)wqh, 884736);
    cvt_kernel<<<2304,  256>>>((const float4*)w_o,   (uint32_t*)woh, 589824);

    dim3 g1(QKVD / 128, NTOK / 128);
    gemm_h1<1><<<g1, 256>>>(xh, wqh, nullptr, qkvh, NTOK, QKVD, DM);

    rope_kernel<<<NTOK, 256>>>();

    attn_kernel<<<4096, 128, 44544>>>();

    dim3 g2(DM / 128, NTOK / 128);
    gemm_h1<0><<<g2, 256>>>(ath, woh, out, nullptr, NTOK, DM, DM);
}